// round 17
// baseline (speedup 1.0000x reference)
#include <cuda_runtime.h>
#include <cuda_bf16.h>
#include <math.h>
#include <stdint.h>

// Shapes (fixed)
#define BB 32
#define TT 512
#define AA 64
#define DD 128
#define HH 256
#define MM (BB*TT)     // 16384
#define NN (DD*DD)     // 16384
#define KK HH          // 256
#define KP 512         // packed cols/row: per 32-k tile, [hi 32 | lo 32]

// Device scratch (allocation-free rule)
__device__ __align__(128) __nv_bfloat16 g_A2[(size_t)MM * KP];    // 16.7 MB
__device__ __align__(128) __nv_bfloat16 g_B2T[(size_t)NN * KP];   // 16.7 MB
__device__ __align__(128) float g_trans[(size_t)MM * NN];         // 1.07 GB
__device__ float g_state[BB][DD];                                 // scan handoff

// ---------------------------------------------------------------------------
// PTX helpers
// ---------------------------------------------------------------------------
__device__ __forceinline__ uint32_t smem_u32(const void* p) {
    uint32_t a;
    asm("{ .reg .u64 t; cvta.to.shared.u64 t, %1; cvt.u32.u64 %0, t; }" : "=r"(a) : "l"(p));
    return a;
}
__device__ __forceinline__ void cp16(uint32_t dst, const void* src) {
    asm volatile("cp.async.cg.shared.global [%0], [%1], 16;" :: "r"(dst), "l"(src) : "memory");
}
__device__ __forceinline__ void cp_commit() {
    asm volatile("cp.async.commit_group;" ::: "memory");
}
template <int N>
__device__ __forceinline__ void cp_wait() {
    asm volatile("cp.async.wait_group %0;" :: "n"(N) : "memory");
}
__device__ __forceinline__ void ldsm4(uint32_t* r, uint32_t addr) {
    asm volatile("ldmatrix.sync.aligned.m8n8.x4.shared.b16 {%0,%1,%2,%3}, [%4];"
                 : "=r"(r[0]), "=r"(r[1]), "=r"(r[2]), "=r"(r[3]) : "r"(addr));
}
__device__ __forceinline__ void mma_bf16(float* d, const uint32_t* a, const uint32_t* b) {
    asm volatile(
        "mma.sync.aligned.m16n8k16.row.col.f32.bf16.bf16.f32 "
        "{%0,%1,%2,%3}, {%4,%5,%6,%7}, {%8,%9}, {%0,%1,%2,%3};"
        : "+f"(d[0]), "+f"(d[1]), "+f"(d[2]), "+f"(d[3])
        : "r"(a[0]), "r"(a[1]), "r"(a[2]), "r"(a[3]), "r"(b[0]), "r"(b[1]));
}
__device__ __forceinline__ float4 ldg_cs4(const float* p) {
    float4 v;
    asm volatile("ld.global.cs.v4.f32 {%0,%1,%2,%3}, [%4];"
                 : "=f"(v.x), "=f"(v.y), "=f"(v.z), "=f"(v.w) : "l"(p));
    return v;
}
__device__ __forceinline__ void stg_cs2(float* p, float2 v) {
    asm volatile("st.global.cs.v2.f32 [%0], {%1,%2};" :: "l"(p), "f"(v.x), "f"(v.y) : "memory");
}
__device__ __forceinline__ uint32_t swoff(uint32_t row, uint32_t kb) {
    return row * 128u + (kb ^ ((row & 7u) << 4));
}

// ---------------------------------------------------------------------------
// Kernel 1: h = relu(actions@w1+b1); write A2 packed [hi|lo] per 32-k tile
// ---------------------------------------------------------------------------
__global__ __launch_bounds__(256) void mlp1_kernel(const float* __restrict__ actions,
                                                   const float* __restrict__ w1,
                                                   const float* __restrict__ b1)
{
    __shared__ float as[8][AA];
    const int tid = threadIdx.x;
    const int m0 = blockIdx.x * 8;

    for (int i = tid; i < 8 * AA; i += 256)
        as[i >> 6][i & 63] = actions[(size_t)m0 * AA + i];
    __syncthreads();

    const int n = tid;
    float bv = b1[n];
    float acc[8];
#pragma unroll
    for (int r = 0; r < 8; r++) acc[r] = bv;
#pragma unroll 8
    for (int a = 0; a < AA; a++) {
        float w = w1[(size_t)a * HH + n];
#pragma unroll
        for (int r = 0; r < 8; r++) acc[r] = fmaf(as[r][a], w, acc[r]);
    }
    const int koff = (n >> 5) * 64 + (n & 31);
#pragma unroll
    for (int r = 0; r < 8; r++) {
        float v = fmaxf(acc[r], 0.0f);
        __nv_bfloat16 hi = __float2bfloat16_rn(v);
        __nv_bfloat16 lo = __float2bfloat16_rn(v - __bfloat162float(hi));
        size_t row = (size_t)(m0 + r) * KP;
        g_A2[row + koff] = hi;
        g_A2[row + koff + 32] = lo;
    }
}

// ---------------------------------------------------------------------------
// Kernel 1b: B2T[n] packed [hi|lo] per 32-k tile (transpose of w2)
// ---------------------------------------------------------------------------
__global__ __launch_bounds__(256) void bprep_kernel(const float* __restrict__ w2)
{
    __shared__ float tile[32][33];
    const int tx = threadIdx.x;
    const int ty = threadIdx.y;
    const int n0 = blockIdx.x * 32;
    const int k0 = blockIdx.y * 32;
#pragma unroll
    for (int i = 0; i < 4; i++) {
        int k = k0 + ty + i * 8;
        tile[ty + i * 8][tx] = w2[(size_t)k * NN + n0 + tx];
    }
    __syncthreads();
    const int k = k0 + tx;
    const int koff = (k >> 5) * 64 + (k & 31);
#pragma unroll
    for (int i = 0; i < 4; i++) {
        int nrow = ty + i * 8;
        float v = tile[tx][nrow];
        __nv_bfloat16 hi = __float2bfloat16_rn(v);
        __nv_bfloat16 lo = __float2bfloat16_rn(v - __bfloat162float(hi));
        size_t row = (size_t)(n0 + nrow) * KP + koff;
        g_B2T[row] = hi;
        g_B2T[row + 32] = lo;
    }
}

// ---------------------------------------------------------------------------
// GEMM common pieces
// ---------------------------------------------------------------------------
#define BMG 128
#define BNG 128
#define NKT 8
#define NSTG 3
#define A_BYTES (BMG*128)
#define B_BYTES (BNG*128)
#define STAGE_BYTES (A_BYTES + B_BYTES)
#define ROWB (KP*2)
#define NPCTA 296            // persistent CTAs (2 per SM x 148)
#define NTILES_A (96*128)    // 12288 tiles for t-chunks 0..2

// per-warp fragment mapping (shared by both gemm kernels)
struct GemmCtx {
    uint32_t a_row, a_hk, b_row, b_hk;
    int m_w, n_w;
};
__device__ __forceinline__ GemmCtx gemm_ctx(int tid) {
    GemmCtx c;
    const int wid = tid >> 5, lane = tid & 31;
    c.m_w = (wid >> 2) * 64;
    c.n_w = (wid & 3) * 32;
    c.a_row = c.m_w + (lane & 7) + (lane & 8);
    c.a_hk  = (lane >> 4) << 4;
    c.b_row = c.n_w + (lane & 7) + ((lane >> 4) << 3);
    c.b_hk  = (lane & 8) << 1;
    return c;
}

// k-tile compute: 3 passes (AHxBH, AHxBL, ALxBH) on stage at sbase
__device__ __forceinline__ void gemm_ktile(const GemmCtx& c, uint32_t abase,
                                           uint32_t bbase, float acc[4][4][4]) {
#pragma unroll
    for (int ks = 0; ks < 2; ks++) {
        const uint32_t akb_h = ks * 32 + c.a_hk;
        const uint32_t bkb_h = ks * 32 + c.b_hk;
        uint32_t ah[4][4], bh[2][4];
#pragma unroll
        for (int mi = 0; mi < 4; mi++)
            ldsm4(ah[mi], abase + swoff(c.a_row + mi * 16, akb_h));
#pragma unroll
        for (int nj = 0; nj < 2; nj++)
            ldsm4(bh[nj], bbase + swoff(c.b_row + nj * 16, bkb_h));
#pragma unroll
        for (int mi = 0; mi < 4; mi++)
#pragma unroll
            for (int nj = 0; nj < 2; nj++) {
                mma_bf16(acc[mi][2 * nj],     ah[mi], &bh[nj][0]);
                mma_bf16(acc[mi][2 * nj + 1], ah[mi], &bh[nj][2]);
            }
        {
            uint32_t bl[2][4];
#pragma unroll
            for (int nj = 0; nj < 2; nj++)
                ldsm4(bl[nj], bbase + swoff(c.b_row + nj * 16, 64 + bkb_h));
#pragma unroll
            for (int mi = 0; mi < 4; mi++)
#pragma unroll
                for (int nj = 0; nj < 2; nj++) {
                    mma_bf16(acc[mi][2 * nj],     ah[mi], &bl[nj][0]);
                    mma_bf16(acc[mi][2 * nj + 1], ah[mi], &bl[nj][2]);
                }
        }
#pragma unroll
        for (int mi = 0; mi < 4; mi++)
            ldsm4(ah[mi], abase + swoff(c.a_row + mi * 16, 64 + akb_h));
#pragma unroll
        for (int mi = 0; mi < 4; mi++)
#pragma unroll
            for (int nj = 0; nj < 2; nj++) {
                mma_bf16(acc[mi][2 * nj],     ah[mi], &bh[nj][0]);
                mma_bf16(acc[mi][2 * nj + 1], ah[mi], &bh[nj][2]);
            }
    }
}

// stage loader (both kernels): tile coords (m0,n0), k-tile kt, stage s
__device__ __forceinline__ void gemm_load(uint32_t dyn, int tid, int s, int kt,
                                          int m0, int n0) {
    uint32_t sb = dyn + s * STAGE_BYTES;
    size_t kbyte = (size_t)kt * 128;
    const char* Abase = (const char*)g_A2;
    const char* Bbase = (const char*)g_B2T;
#pragma unroll
    for (int i = 0; i < 4; i++) {
        int q = i * 256 + tid;
        uint32_t r = q >> 3, cc = (q & 7) * 16;
        cp16(sb + swoff(r, cc), Abase + (size_t)(m0 + r) * ROWB + kbyte + cc);
    }
#pragma unroll
    for (int i = 0; i < 4; i++) {
        int q = i * 256 + tid;
        uint32_t r = q >> 3, cc = (q & 7) * 16;
        cp16(sb + A_BYTES + swoff(r, cc), Bbase + (size_t)(n0 + r) * ROWB + kbyte + cc);
    }
    cp_commit();
}

// epilogue: direct stores with gmem bias loads (no smem, no extra sync)
__device__ __forceinline__ void gemm_epi(const GemmCtx& c, int tid, int m0, int n0,
                                         const float* __restrict__ bias,
                                         float acc[4][4][4]) {
    const int lane = tid & 31;
    const int cl = 2 * (lane & 3);
    const int rl = lane >> 2;
#pragma unroll
    for (int mi = 0; mi < 4; mi++) {
        int row0 = m0 + c.m_w + mi * 16 + rl;
#pragma unroll
        for (int nt = 0; nt < 4; nt++) {
            int col = n0 + c.n_w + nt * 8 + cl;
            float bx = __ldg(bias + col), by = __ldg(bias + col + 1);
            float2 v0 = {acc[mi][nt][0] + bx, acc[mi][nt][1] + by};
            float2 v1 = {acc[mi][nt][2] + bx, acc[mi][nt][3] + by};
            stg_cs2(g_trans + (size_t)row0 * NN + col, v0);
            stg_cs2(g_trans + (size_t)(row0 + 8) * NN + col, v1);
        }
    }
}

__device__ __forceinline__ void tile_coords(int idx, int& m0, int& n0) {
    int x = idx & 127, ylin = idx >> 7;
    m0 = ((ylin & 31) * 4 + (ylin >> 5)) * BMG;
    n0 = x * BNG;
}

// ---------------------------------------------------------------------------
// Kernel 2a: PERSISTENT gemm over tiles [0, NTILES_A) — cp.async ring runs
// continuously across tile boundaries (no per-tile prologue/drain).
// ---------------------------------------------------------------------------
__global__ __launch_bounds__(256, 2) void gemmA_pers(const float* __restrict__ bias)
{
    extern __shared__ char dsm[];
    const uint32_t dyn = smem_u32(dsm);
    const int tid = threadIdx.x;
    const int bid = blockIdx.x;
    const GemmCtx c = gemm_ctx(tid);

    const int myt = (NTILES_A - 1 - bid) / NPCTA + 1;   // tiles for this CTA
    const int total = myt * NKT;                         // global steps

    auto load_step = [&](int g) {
        int ti = g >> 3, kt = g & 7;
        int m0, n0;
        tile_coords(bid + ti * NPCTA, m0, n0);
        gemm_load(dyn, tid, g % NSTG, kt, m0, n0);
    };

    float acc[4][4][4];
#pragma unroll
    for (int mi = 0; mi < 4; mi++)
#pragma unroll
        for (int nt = 0; nt < 4; nt++)
#pragma unroll
            for (int e = 0; e < 4; e++) acc[mi][nt][e] = 0.0f;

    load_step(0);
    if (total > 1) load_step(1);

#pragma unroll 1
    for (int g = 0; g < total; g++) {
        if (g + 1 < total) cp_wait<1>();
        else               cp_wait<0>();
        __syncthreads();
        if (g + 2 < total) load_step(g + 2);

        gemm_ktile(c, dyn + (g % NSTG) * STAGE_BYTES,
                   dyn + (g % NSTG) * STAGE_BYTES + A_BYTES, acc);

        if ((g & 7) == 7) {
            int m0, n0;
            tile_coords(bid + (g >> 3) * NPCTA, m0, n0);
            gemm_epi(c, tid, m0, n0, bias, acc);
#pragma unroll
            for (int mi = 0; mi < 4; mi++)
#pragma unroll
                for (int nt = 0; nt < 4; nt++)
#pragma unroll
                    for (int e = 0; e < 4; e++) acc[mi][nt][e] = 0.0f;
        }
    }
}

// ---------------------------------------------------------------------------
// Kernel 2b: non-persistent gemm (R16 structure) for t-chunk 3, concurrent
// with scanA.
// ---------------------------------------------------------------------------
__global__ __launch_bounds__(256, 2) void gemm8_kernel(const float* __restrict__ bias,
                                                       int yoff)
{
    extern __shared__ char dsm[];
    const uint32_t dyn = smem_u32(dsm);
    const int tid = threadIdx.x;
    const GemmCtx c = gemm_ctx(tid);
    int m0, n0;
    tile_coords((blockIdx.y + yoff) * 128 + blockIdx.x, m0, n0);

    gemm_load(dyn, tid, 0, 0, m0, n0);
    gemm_load(dyn, tid, 1, 1, m0, n0);

    float acc[4][4][4];
#pragma unroll
    for (int mi = 0; mi < 4; mi++)
#pragma unroll
        for (int nt = 0; nt < 4; nt++)
#pragma unroll
            for (int e = 0; e < 4; e++) acc[mi][nt][e] = 0.0f;

#pragma unroll 1
    for (int kt = 0; kt < NKT; kt++) {
        if (kt + 1 < NKT) cp_wait<1>();
        else              cp_wait<0>();
        __syncthreads();
        if (kt + 2 < NKT) gemm_load(dyn, tid, (kt + 2) % NSTG, kt + 2, m0, n0);

        gemm_ktile(c, dyn + (kt % NSTG) * STAGE_BYTES,
                   dyn + (kt % NSTG) * STAGE_BYTES + A_BYTES, acc);
    }

    gemm_epi(c, tid, m0, n0, bias, acc);
}

// ---------------------------------------------------------------------------
// Scan (R16 measured structure, unchanged)
// ---------------------------------------------------------------------------
template <int T0, int T1>
__device__ __forceinline__ void scan_range(const float* __restrict__ Tb, int b,
                                           float* __restrict__ out,
                                           float (*s_nx)[DD], float (*red)[DD],
                                           float* wsum)
{
    const int tid = threadIdx.x;
    const int w = tid >> 5;
    const int l = tid & 31;
    const int cch = w;
    const int j = l * 4;

    float4 cur[8];
#pragma unroll
    for (int ii = 0; ii < 8; ii++)
        cur[ii] = ldg_cs4(Tb + (size_t)T0 * NN + (size_t)(cch * 8 + ii) * DD + j);
    __syncthreads();

#pragma unroll 1
    for (int t = T0; t < T1; t++) {
        const int rb = (t & 1) ^ 1;
        const int wb = t & 1;

        float4 nxt[8];
        if (t + 1 < T1) {
            const float* Tn = Tb + (size_t)(t + 1) * NN;
#pragma unroll
            for (int ii = 0; ii < 8; ii++)
                nxt[ii] = ldg_cs4(Tn + (size_t)(cch * 8 + ii) * DD + j);
        }

        float4 p = {0.0f, 0.0f, 0.0f, 0.0f};
#pragma unroll
        for (int ii = 0; ii < 8; ii++) {
            float sv = s_nx[rb][cch * 8 + ii];
            p.x = fmaf(sv, cur[ii].x, p.x);
            p.y = fmaf(sv, cur[ii].y, p.y);
            p.z = fmaf(sv, cur[ii].z, p.z);
            p.w = fmaf(sv, cur[ii].w, p.w);
        }
        *(float4*)&red[cch][j] = p;

        if (w >= 12) {
            const int k = w - 12;
            float sv = s_nx[rb][k * 32 + l];
            float sq = sv * sv;
#pragma unroll
            for (int o = 16; o; o >>= 1) sq += __shfl_xor_sync(0xffffffffu, sq, o);
            if (l == 0) wsum[k] = sq;
        }
        __syncthreads();

        if (tid < DD) {
            float s0 = red[0][tid] + red[1][tid];
            float s1 = red[2][tid] + red[3][tid];
            float s2 = red[4][tid] + red[5][tid];
            float s3 = red[6][tid] + red[7][tid];
            float s4 = red[8][tid] + red[9][tid];
            float s5 = red[10][tid] + red[11][tid];
            float s6 = red[12][tid] + red[13][tid];
            float s7 = red[14][tid] + red[15][tid];
            float v = ((s0 + s1) + (s2 + s3)) + ((s4 + s5) + (s6 + s7));
            v = fmaxf(v, 0.0f);

            float inv = rsqrtf(fmaxf((wsum[0] + wsum[1]) + (wsum[2] + wsum[3]), 1e-24f));
            if (t > 0)
                out[((size_t)b * TT + (t - 1)) * DD + tid] = s_nx[rb][tid] * inv;
            s_nx[wb][tid] = v * inv;
        }
#pragma unroll
        for (int ii = 0; ii < 8; ii++) cur[ii] = nxt[ii];
        __syncthreads();
    }
}

#define TSPLIT 384

__global__ __launch_bounds__(512, 1) void scanA_kernel(const float* __restrict__ init_s,
                                                       float* __restrict__ out)
{
    __shared__ float s_nx[2][DD];
    __shared__ float red[16][DD];
    __shared__ float wsum[4];

    const int tid = threadIdx.x;
    const int b = blockIdx.x;
    const float* Tb = g_trans + (size_t)b * TT * (size_t)NN;

    if (tid < DD) s_nx[1][tid] = init_s[tid];

    scan_range<0, TSPLIT>(Tb, b, out, s_nx, red, wsum);

    if (tid < DD) g_state[b][tid] = s_nx[(TSPLIT - 1) & 1][tid];
}

__global__ __launch_bounds__(512, 1) void scanB_kernel(float* __restrict__ out)
{
    __shared__ float s_nx[2][DD];
    __shared__ float red[16][DD];
    __shared__ float wsum[4];

    const int tid = threadIdx.x;
    const int w = tid >> 5;
    const int l = tid & 31;
    const int b = blockIdx.x;
    const float* Tb = g_trans + (size_t)b * TT * (size_t)NN;

    if (tid < DD) s_nx[(TSPLIT & 1) ^ 1][tid] = g_state[b][tid];

    scan_range<TSPLIT, TT>(Tb, b, out, s_nx, red, wsum);

    const int fb = (TT - 1) & 1;
    if (w >= 12) {
        const int k = w - 12;
        float sv = s_nx[fb][k * 32 + l];
        float sq = sv * sv;
#pragma unroll
        for (int o = 16; o; o >>= 1) sq += __shfl_xor_sync(0xffffffffu, sq, o);
        if (l == 0) wsum[k] = sq;
    }
    __syncthreads();
    if (tid < DD) {
        float inv = rsqrtf(fmaxf((wsum[0] + wsum[1]) + (wsum[2] + wsum[3]), 1e-24f));
        out[((size_t)b * TT + (TT - 1)) * DD + tid] = s_nx[fb][tid] * inv;
    }
}

// ---------------------------------------------------------------------------
extern "C" void kernel_launch(void* const* d_in, const int* in_sizes, int n_in,
                              void* d_out, int out_size)
{
    const float* actions = (const float*)d_in[0];
    const float* init_s  = (const float*)d_in[1];
    const float* w1      = (const float*)d_in[2];
    const float* b1      = (const float*)d_in[3];
    const float* w2      = (const float*)d_in[4];
    const float* b2      = (const float*)d_in[5];
    float* out = (float*)d_out;

    static bool s_init = false;
    static cudaStream_t s2;
    static cudaEvent_t evF, evP, evA, evB, evJ;
    if (!s_init) {
        cudaStreamCreateWithFlags(&s2, cudaStreamNonBlocking);
        cudaEventCreateWithFlags(&evF, cudaEventDisableTiming);
        cudaEventCreateWithFlags(&evP, cudaEventDisableTiming);
        cudaEventCreateWithFlags(&evA, cudaEventDisableTiming);
        cudaEventCreateWithFlags(&evB, cudaEventDisableTiming);
        cudaEventCreateWithFlags(&evJ, cudaEventDisableTiming);
        s_init = true;
    }

    cudaFuncSetAttribute(gemmA_pers, cudaFuncAttributeMaxDynamicSharedMemorySize,
                         NSTG * STAGE_BYTES);
    cudaFuncSetAttribute(gemm8_kernel, cudaFuncAttributeMaxDynamicSharedMemorySize,
                         NSTG * STAGE_BYTES);

    // Legal capture fork: record on origin stream FIRST, then s2 waits on it.
    cudaEventRecord(evF, 0);
    cudaStreamWaitEvent(s2, evF, 0);

    // mlp1 (stream 0) ∥ bprep (stream s2)
    mlp1_kernel<<<MM / 8, 256>>>(actions, w1, b1);
    bprep_kernel<<<dim3(NN / 32, KK / 32), dim3(32, 8), 0, s2>>>(w2);
    cudaEventRecord(evP, s2);
    cudaStreamWaitEvent(0, evP, 0);

    // gemmA: persistent, tiles for t-chunks 0..2 (t in [0,384))
    gemmA_pers<<<NPCTA, 256, NSTG * STAGE_BYTES>>>(b2);
    cudaEventRecord(evA, 0);

    // scanA on s2, concurrent with gemmB
    cudaStreamWaitEvent(s2, evA, 0);
    scanA_kernel<<<BB, 512, 0, s2>>>(init_s, out);

    // gemmB: t-chunk 3 (t in [384,512)), non-persistent
    gemm8_kernel<<<dim3(NN / BNG, 32), 256, NSTG * STAGE_BYTES>>>(b2, 96);
    cudaEventRecord(evB, 0);

    // scanB after gemmB (and after scanA by s2 stream order)
    cudaStreamWaitEvent(s2, evB, 0);
    scanB_kernel<<<BB, 512, 0, s2>>>(out);

    // join back to the main stream
    cudaEventRecord(evJ, s2);
    cudaStreamWaitEvent(0, evJ, 0);
}